// round 14
// baseline (speedup 1.0000x reference)
#include <cuda_runtime.h>
#include <cuda_fp16.h>
#include <cstdint>

#define T_LEN 8192
#define CCH   512
#define BATCH 8
#define NELEM (BATCH * CCH * T_LEN)

__device__ float  g_buf2[NELEM];            // conv1 output (f32, [B][C][T])
__device__ __half g_bufH[NELEM];            // act output   (f16, [B][C][T])
__device__ __half g_bufT[NELEM];            // transposed   (f16, [B][T][C])

// Pre-permuted f16 weights, fragment order:
// u = (((cb*16 + st)*6 + (kk*2+ks))*8 + mt)*32 + lane   (uint4 each)
#define WPERM_U4 (4 * 16 * 6 * 8 * 32)     // 98304 uint4 = 1.5 MB
__device__ uint4 g_wperm1[WPERM_U4];
__device__ uint4 g_wperm2[WPERM_U4];

// ---------------------------------------------------------------------------
__device__ __forceinline__ uint32_t smem_u32(const void* p) {
    uint32_t a;
    asm("{ .reg .u64 t; cvta.to.shared.u64 t, %1; cvt.u32.u64 %0, t; }"
        : "=r"(a) : "l"(p));
    return a;
}
__device__ __forceinline__ uint32_t pack_f16x2(float lo, float hi) {
    uint32_t r;
    asm("cvt.rn.f16x2.f32 %0, %1, %2;" : "=r"(r) : "f"(hi), "f"(lo));
    return r;
}
__device__ __forceinline__ void cp_async16(uint32_t dst, const void* src) {
    asm volatile("cp.async.cg.shared.global [%0], [%1], 16;"
                 :: "r"(dst), "l"(src));
}
__device__ __forceinline__ void cp_async16s(uint32_t dst, const void* src, uint32_t sz) {
    asm volatile("cp.async.cg.shared.global [%0], [%1], 16, %2;"
                 :: "r"(dst), "l"(src), "r"(sz));
}
__device__ __forceinline__ void cp_commit() {
    asm volatile("cp.async.commit_group;" ::: "memory");
}
template <int N>
__device__ __forceinline__ void cp_wait() {
    asm volatile("cp.async.wait_group %0;" :: "n"(N) : "memory");
}
__device__ __forceinline__ void mma_f16(float* d, const uint32_t* a, const uint32_t* b) {
    asm volatile(
        "mma.sync.aligned.m16n8k16.row.col.f32.f16.f16.f32 "
        "{%0,%1,%2,%3}, {%4,%5,%6,%7}, {%8,%9}, {%0,%1,%2,%3};"
        : "+f"(d[0]), "+f"(d[1]), "+f"(d[2]), "+f"(d[3])
        : "r"(a[0]), "r"(a[1]), "r"(a[2]), "r"(a[3]), "r"(b[0]), "r"(b[1]));
}
__device__ __forceinline__ void ldsm_x4(uint32_t& r0, uint32_t& r1,
                                        uint32_t& r2, uint32_t& r3, uint32_t addr) {
    asm volatile("ldmatrix.sync.aligned.m8n8.x4.shared.b16 {%0,%1,%2,%3}, [%4];"
                 : "=r"(r0), "=r"(r1), "=r"(r2), "=r"(r3) : "r"(addr));
}

// ---------------------------------------------------------------------------
// Weight permutation: K-dim = ci (3 separate kk GEMMs).
// ---------------------------------------------------------------------------
__global__ __launch_bounds__(256) void permute_w(
    const float* __restrict__ w, uint4* __restrict__ wp)
{
    const int u = blockIdx.x * 256 + threadIdx.x;   // 0..98303
    const int lane = u & 31;
    const int rest = u >> 5;
    const int mt = rest & 7;
    const int g  = (rest >> 3) % 6;
    const int sc = (rest >> 3) / 6;
    const int ks = g & 1;
    const int kk = g >> 1;
    const int st = sc & 15;
    const int cb = sc >> 4;

    uint4 v;
    uint32_t* o = &v.x;
#pragma unroll
    for (int rg = 0; rg < 4; ++rg) {
        const int m8 = (lane >> 2) + 8 * (rg & 1);
        const int ci = st * 32 + ks * 16 + 2 * (lane & 3) + 8 * (rg >> 1);
        const int co = cb * 128 + mt * 16 + m8;
        const float w0 = w[(size_t)co * 1536 + ci * 3 + kk];
        const float w1 = w[(size_t)co * 1536 + (ci + 1) * 3 + kk];
        o[rg] = pack_f16x2(w0, w1);
    }
    wp[u] = v;
}

// ---------------------------------------------------------------------------
// Act v4: register-window upsample, f16 output [B][C][T].
// ---------------------------------------------------------------------------
__global__ __launch_bounds__(256) void act_kernel(
    const float* __restrict__ in, __half* __restrict__ out,
    const float* __restrict__ la, const float* __restrict__ lb,
    const float* __restrict__ fup, const float* __restrict__ fdn)
{
    __shared__ __align__(16) float sx[1040];
    __shared__ __align__(16) float sv[2064];
    __shared__ float su[12], sd[12];

    const int row = blockIdx.y;
    const int c   = row & (CCH - 1);
    const int t0  = blockIdx.x * 1024;
    const int tid = threadIdx.x;

    if (tid < 12) { su[tid] = fup[tid]; sd[tid] = fdn[tid]; }

    const float* xrow = in + (size_t)row * T_LEN;
#pragma unroll
    for (int it = 0; it < 5; ++it) {
        const int i = it * 256 + tid;
        if (i < 1040) {
            int g = t0 - 8 + i;
            g = min(max(g, 0), T_LEN - 1);
            sx[i] = xrow[g];
        }
    }
    __syncthreads();

    const float alpha = expf(la[c]);
    const float invb  = 1.0f / (expf(lb[c]) + 1e-9f);

    float u0=su[0],u1=su[1],u2=su[2],u3=su[3],u4=su[4],u5=su[5],
          u6=su[6],u7=su[7],u8=su[8],u9=su[9],u10=su[10],u11=su[11];

    {
        float xr[12];
        const float4 a0 = *reinterpret_cast<const float4*>(&sx[tid * 4]);
        const float4 a1 = *reinterpret_cast<const float4*>(&sx[tid * 4 + 4]);
        const float4 a2 = *reinterpret_cast<const float4*>(&sx[tid * 4 + 8]);
        xr[0]=a0.x; xr[1]=a0.y; xr[2]=a0.z; xr[3]=a0.w;
        xr[4]=a1.x; xr[5]=a1.y; xr[6]=a1.z; xr[7]=a1.w;
        xr[8]=a2.x; xr[9]=a2.y; xr[10]=a2.z; xr[11]=a2.w;

        float v[8];
#pragma unroll
        for (int m = 0; m < 4; ++m) {
            float ua = u0*xr[8+m] + u2*xr[7+m] + u4*xr[6+m]
                     + u6*xr[5+m] + u8*xr[4+m] + u10*xr[3+m];
            float ub = u1*xr[8+m] + u3*xr[7+m] + u5*xr[6+m]
                     + u7*xr[5+m] + u9*xr[4+m] + u11*xr[3+m];
            ua *= 2.0f; ub *= 2.0f;
            const float sa = __sinf(ua * alpha);
            const float sb = __sinf(ub * alpha);
            v[2*m]   = ua + sa * sa * invb;
            v[2*m+1] = ub + sb * sb * invb;
        }
        float4 o0, o1;
        o0.x=v[0]; o0.y=v[1]; o0.z=v[2]; o0.w=v[3];
        o1.x=v[4]; o1.y=v[5]; o1.z=v[6]; o1.w=v[7];
        *reinterpret_cast<float4*>(&sv[tid * 8])     = o0;
        *reinterpret_cast<float4*>(&sv[tid * 8 + 4]) = o1;
    }
    if (tid < 16) {
        const int i = 2048 + tid;
        const int tp = 2 * t0 - 5 + i;
        const int sx_off = 8 - t0;
        float u;
        if (tp & 1) {
            const int h = (tp + 5) >> 1;
            const float* p = &sx[h + sx_off];
            u = u0*p[0] + u2*p[-1] + u4*p[-2] + u6*p[-3] + u8*p[-4] + u10*p[-5];
        } else {
            const int h = tp >> 1;
            const float* p = &sx[h + sx_off];
            u = u1*p[2] + u3*p[1] + u5*p[0] + u7*p[-1] + u9*p[-2] + u11*p[-3];
        }
        u *= 2.0f;
        const float s = __sinf(u * alpha);
        sv[i] = u + s * s * invb;
    }
    __syncthreads();

    if (t0 == 0 && tid < 5) sv[tid] = sv[5];
    if (t0 == T_LEN - 1024 && tid < 11) sv[2053 + tid] = sv[2052];
    __syncthreads();

    {
        float d0=sd[0],d1=sd[1],d2=sd[2],d3=sd[3],d4=sd[4],d5=sd[5],
              d6=sd[6],d7=sd[7],d8=sd[8],d9=sd[9],d10=sd[10],d11=sd[11];
        const float4 w0 = *reinterpret_cast<const float4*>(&sv[tid * 8]);
        const float4 w1 = *reinterpret_cast<const float4*>(&sv[tid * 8 + 4]);
        const float4 w2 = *reinterpret_cast<const float4*>(&sv[tid * 8 + 8]);
        const float4 w3 = *reinterpret_cast<const float4*>(&sv[tid * 8 + 12]);
        const float4 w4 = *reinterpret_cast<const float4*>(&sv[tid * 8 + 16]);
        float v[20];
        v[0]=w0.x; v[1]=w0.y; v[2]=w0.z; v[3]=w0.w;
        v[4]=w1.x; v[5]=w1.y; v[6]=w1.z; v[7]=w1.w;
        v[8]=w2.x; v[9]=w2.y; v[10]=w2.z; v[11]=w2.w;
        v[12]=w3.x; v[13]=w3.y; v[14]=w3.z; v[15]=w3.w;
        v[16]=w4.x; v[17]=w4.y; v[18]=w4.z; v[19]=w4.w;
        float z[4];
#pragma unroll
        for (int o = 0; o < 4; ++o) {
            const float* p = v + 2 * o;
            z[o] = d0*p[0] + d1*p[1] + d2*p[2] + d3*p[3] + d4*p[4] + d5*p[5]
                 + d6*p[6] + d7*p[7] + d8*p[8] + d9*p[9] + d10*p[10] + d11*p[11];
        }
        uint2 st;
        st.x = pack_f16x2(z[0], z[1]);
        st.y = pack_f16x2(z[2], z[3]);
        *reinterpret_cast<uint2*>(out + (size_t)row * T_LEN + t0 + tid * 4) = st;
    }
}

// ---------------------------------------------------------------------------
// Transpose: f16 [B][C][T] -> f16 [B][T][C].  Tile 32c x 64t.
// ---------------------------------------------------------------------------
__global__ __launch_bounds__(256) void transpose_cvt(
    const __half* __restrict__ in, __half* __restrict__ out)
{
    __shared__ float sx[32][65];
    const int t0 = blockIdx.x * 64;
    const int c0 = blockIdx.y * 32;
    const int b  = blockIdx.z;
    const int tid = threadIdx.x;

    {
        const int cl = tid >> 3;
        const int t8 = (tid & 7) * 8;
        const __half* src = in + ((size_t)(b * CCH + c0 + cl)) * T_LEN + t0 + t8;
        uint4 v = *reinterpret_cast<const uint4*>(src);
        const __half2* hp = reinterpret_cast<const __half2*>(&v);
#pragma unroll
        for (int j = 0; j < 4; ++j) {
            float2 f = __half22float2(hp[j]);
            sx[cl][t8 + 2*j]     = f.x;
            sx[cl][t8 + 2*j + 1] = f.y;
        }
    }
    __syncthreads();
    {
        const int tl = tid >> 2;
        const int cg = (tid & 3) * 8;
        uint4 o;
        o.x = pack_f16x2(sx[cg+0][tl], sx[cg+1][tl]);
        o.y = pack_f16x2(sx[cg+2][tl], sx[cg+3][tl]);
        o.z = pack_f16x2(sx[cg+4][tl], sx[cg+5][tl]);
        o.w = pack_f16x2(sx[cg+6][tl], sx[cg+7][tl]);
        *reinterpret_cast<uint4*>(out + ((size_t)(b * T_LEN + t0 + tl)) * CCH + c0 + cg) = o;
    }
}

// ---------------------------------------------------------------------------
// fp16 HMMA conv, 3 shifted GEMMs over K=ci. Block 128co x 256t, 512 threads,
// 16 warps (4x4: warp tile 32co x 64t). 3-stage cp.async pipeline; A L2
// traffic halved vs 128t tiles. 135.6KB smem, 1 CTA/SM (16 warps).
// ---------------------------------------------------------------------------
#define NST 16
#define BP  20
#define NTILE 256
#define BROWS (NTILE + 2)                    // 258
#define ASTAGE_W 6144                        // 24576 B
#define BSTAGE_W (BROWS * BP)                // 5160 words
#define STAGE_W  (ASTAGE_W + BSTAGE_W)       // 11304 words
#define CONV_SMEM (3 * STAGE_W * 4)          // 135648 B

__global__ __launch_bounds__(512, 1)
void conv_tc(const __half* __restrict__ xt, const uint4* __restrict__ wperm,
             const float* __restrict__ bias, const float* __restrict__ resid,
             float* __restrict__ out)
{
    extern __shared__ uint32_t Ssm[];

    const int tid  = threadIdx.x;
    const int wid  = tid >> 5;
    const int lane = tid & 31;
    const int wr   = wid >> 2;       // 0..3: M offset 32*wr
    const int wc   = wid & 3;        // 0..3: N offset 64*wc
    const int b    = blockIdx.z;
    const int cb   = blockIdx.y;
    const int co0  = cb * 128;
    const int t0   = blockIdx.x * NTILE;

    float acc[2][8][4];
#pragma unroll
    for (int i = 0; i < 2; i++)
#pragma unroll
        for (int j = 0; j < 8; j++)
#pragma unroll
            for (int r = 0; r < 4; r++) acc[i][j][r] = 0.0f;

    const uint32_t smem0 = smem_u32(Ssm);
    const char* browg = reinterpret_cast<const char*>(
        xt + ((size_t)(b * T_LEN + t0 - 1)) * CCH);

    // ldmatrix per-lane base: group g = lane>>3 selects (k-half, n-half)
    const int lg = lane >> 3;
    const int lr = lane & 7;
    const uint32_t lbase = smem0 + ASTAGE_W * 4
        + (uint32_t)((wc * 64 + lr + ((lg & 2) ? 8 : 0)) * (BP * 4))
        + (uint32_t)((lg & 1) * 16);

    auto fill = [&](int st, int s) {
        // A: 1536 uint4/stage over 512 threads = 3 each
        const uint4* Asrc = wperm + ((size_t)(cb * 16 + st)) * 1536 + tid;
        const uint32_t dstA = smem0 + s * (STAGE_W * 4) + tid * 16;
#pragma unroll
        for (int it = 0; it < 3; ++it)
            cp_async16(dstA + it * 8192, Asrc + it * 512);
        // B: 258 rows x 4 segs = 1032 cp16
        const uint32_t dstB = smem0 + s * (STAGE_W * 4) + ASTAGE_W * 4;
        const char* bs = browg + st * 64;
#pragma unroll
        for (int it = 0; it < 3; ++it) {
            const int idx = tid + it * 512;
            if (idx < BROWS * 4) {
                const int row = idx >> 2, seg = idx & 3;
                const int tg = t0 - 1 + row;
                const uint32_t sz = (tg >= 0 && tg < T_LEN) ? 16u : 0u;
                cp_async16s(dstB + row * (BP * 4) + seg * 16,
                            bs + (size_t)row * (CCH * 2) + seg * 16, sz);
            }
        }
        cp_commit();
    };

    // 3-stage prologue
    fill(0, 0);
    fill(1, 1);

    int s = 0;
    for (int st = 0; st < NST; ++st) {
        if (st + 1 < NST) { cp_wait<1>(); } else { cp_wait<0>(); }
        __syncthreads();
        if (st + 2 < NST) {
            int s2 = s + 2; if (s2 >= 3) s2 -= 3;
            fill(st + 2, s2);
        }

        const uint32_t* As = Ssm + s * STAGE_W;
        const uint32_t lB = lbase + s * (STAGE_W * 4);
#pragma unroll
        for (int kk = 0; kk < 3; ++kk) {
#pragma unroll
            for (int ks = 0; ks < 2; ++ks) {
                uint4 afr[2];
#pragma unroll
                for (int mt = 0; mt < 2; ++mt)
                    afr[mt] = *reinterpret_cast<const uint4*>(
                        As + (((kk * 2 + ks) * 8 + wr * 2 + mt) * 32 + lane) * 4);
                uint2 bfr[8];
                const uint32_t bb = lB + kk * (BP * 4) + ks * 32;
#pragma unroll
                for (int ntp = 0; ntp < 4; ++ntp)
                    ldsm_x4(bfr[2*ntp].x, bfr[2*ntp].y,
                            bfr[2*ntp+1].x, bfr[2*ntp+1].y,
                            bb + ntp * (16 * BP * 4));
#pragma unroll
                for (int mt = 0; mt < 2; ++mt)
#pragma unroll
                    for (int nt = 0; nt < 8; ++nt)
                        mma_f16(acc[mt][nt],
                                reinterpret_cast<const uint32_t*>(&afr[mt]),
                                reinterpret_cast<const uint32_t*>(&bfr[nt]));
            }
        }
        if (++s >= 3) s = 0;
    }

    __syncthreads();

    // ---- epilogue ----
    const int gid = lane >> 2;
    const int tig = lane & 3;
#pragma unroll
    for (int mt = 0; mt < 2; ++mt) {
#pragma unroll
        for (int half = 0; half < 2; ++half) {
            const int co = co0 + wr * 32 + mt * 16 + gid + half * 8;
            const float bv = __ldg(bias + co);
            float* orow = out + ((size_t)b * CCH + co) * T_LEN + t0 + wc * 64;
            const float* rrow = resid
                ? resid + ((size_t)b * CCH + co) * T_LEN + t0 + wc * 64 : nullptr;
#pragma unroll
            for (int nt = 0; nt < 8; ++nt) {
                const int n = nt * 8 + tig * 2;
                float lo = acc[mt][nt][half * 2 + 0] + bv;
                float hi = acc[mt][nt][half * 2 + 1] + bv;
                if (rrow) {
                    float2 rv = *reinterpret_cast<const float2*>(rrow + n);
                    lo += rv.x; hi += rv.y;
                }
                float2 v; v.x = lo; v.y = hi;
                *reinterpret_cast<float2*>(orow + n) = v;
            }
        }
    }
}

// ---------------------------------------------------------------------------
extern "C" void kernel_launch(void* const* d_in, const int* in_sizes, int n_in,
                              void* d_out, int out_size)
{
    const float* x    = (const float*)d_in[0];
    const float* a1a  = (const float*)d_in[1];
    const float* a1b  = (const float*)d_in[2];
    const float* a2a  = (const float*)d_in[3];
    const float* a2b  = (const float*)d_in[4];
    const float* c1w  = (const float*)d_in[5];
    const float* c1b  = (const float*)d_in[6];
    const float* c2w  = (const float*)d_in[7];
    const float* c2b  = (const float*)d_in[8];
    const float* fup  = (const float*)d_in[9];
    const float* fdn  = (const float*)d_in[10];
    float* out = (float*)d_out;

    float* g2;
    __half *gH, *gT;
    uint4 *wp1, *wp2;
    cudaGetSymbolAddress((void**)&g2, g_buf2);
    cudaGetSymbolAddress((void**)&gH, g_bufH);
    cudaGetSymbolAddress((void**)&gT, g_bufT);
    cudaGetSymbolAddress((void**)&wp1, g_wperm1);
    cudaGetSymbolAddress((void**)&wp2, g_wperm2);

    cudaFuncSetAttribute(conv_tc, cudaFuncAttributeMaxDynamicSharedMemorySize, CONV_SMEM);

    dim3 gAct(T_LEN / 1024, BATCH * CCH);
    dim3 gTr(T_LEN / 64, CCH / 32, BATCH);
    dim3 gConv(T_LEN / NTILE, CCH / 128, BATCH);

    permute_w<<<384, 256>>>(c1w, wp1);
    permute_w<<<384, 256>>>(c2w, wp2);

    act_kernel<<<gAct, 256>>>(x, gH, a1a, a1b, fup, fdn);
    transpose_cvt<<<gTr, 256>>>(gH, gT);
    conv_tc<<<gConv, 512, CONV_SMEM>>>(gT, wp1, c1b, nullptr, g2);
    act_kernel<<<gAct, 256>>>(g2, gH, a2a, a2b, fup, fdn);
    transpose_cvt<<<gTr, 256>>>(gH, gT);
    conv_tc<<<gConv, 512, CONV_SMEM>>>(gT, wp2, c2b, x, out);
}

// round 15
// speedup vs baseline: 1.0615x; 1.0615x over previous
#include <cuda_runtime.h>
#include <cuda_fp16.h>
#include <cstdint>

#define T_LEN 8192
#define CCH   512
#define BATCH 8
#define NELEM (BATCH * CCH * T_LEN)

__device__ __half g_bufM[NELEM];            // conv1 output (f16, [B][C][T])
__device__ __half g_bufH[NELEM];            // act output   (f16, [B][C][T])
__device__ __half g_bufT[NELEM];            // transposed   (f16, [B][T][C])

// Pre-permuted f16 weights, fragment order:
// u = (((cb*16 + st)*6 + (kk*2+ks))*8 + mt)*32 + lane   (uint4 each)
#define WPERM_U4 (4 * 16 * 6 * 8 * 32)     // 98304 uint4 = 1.5 MB
__device__ uint4 g_wperm1[WPERM_U4];
__device__ uint4 g_wperm2[WPERM_U4];

// ---------------------------------------------------------------------------
__device__ __forceinline__ uint32_t smem_u32(const void* p) {
    uint32_t a;
    asm("{ .reg .u64 t; cvta.to.shared.u64 t, %1; cvt.u32.u64 %0, t; }"
        : "=r"(a) : "l"(p));
    return a;
}
__device__ __forceinline__ uint32_t pack_f16x2(float lo, float hi) {
    uint32_t r;
    asm("cvt.rn.f16x2.f32 %0, %1, %2;" : "=r"(r) : "f"(hi), "f"(lo));
    return r;
}
__device__ __forceinline__ void cp_async16(uint32_t dst, const void* src) {
    asm volatile("cp.async.cg.shared.global [%0], [%1], 16;"
                 :: "r"(dst), "l"(src));
}
__device__ __forceinline__ void cp_async16s(uint32_t dst, const void* src, uint32_t sz) {
    asm volatile("cp.async.cg.shared.global [%0], [%1], 16, %2;"
                 :: "r"(dst), "l"(src), "r"(sz));
}
__device__ __forceinline__ void cp_commit() {
    asm volatile("cp.async.commit_group;" ::: "memory");
}
template <int N>
__device__ __forceinline__ void cp_wait() {
    asm volatile("cp.async.wait_group %0;" :: "n"(N) : "memory");
}
__device__ __forceinline__ void mma_f16(float* d, const uint32_t* a, const uint32_t* b) {
    asm volatile(
        "mma.sync.aligned.m16n8k16.row.col.f32.f16.f16.f32 "
        "{%0,%1,%2,%3}, {%4,%5,%6,%7}, {%8,%9}, {%0,%1,%2,%3};"
        : "+f"(d[0]), "+f"(d[1]), "+f"(d[2]), "+f"(d[3])
        : "r"(a[0]), "r"(a[1]), "r"(a[2]), "r"(a[3]), "r"(b[0]), "r"(b[1]));
}
__device__ __forceinline__ void ldsm_x4(uint32_t& r0, uint32_t& r1,
                                        uint32_t& r2, uint32_t& r3, uint32_t addr) {
    asm volatile("ldmatrix.sync.aligned.m8n8.x4.shared.b16 {%0,%1,%2,%3}, [%4];"
                 : "=r"(r0), "=r"(r1), "=r"(r2), "=r"(r3) : "r"(addr));
}

// ---------------------------------------------------------------------------
// Weight permutation: K-dim = ci (3 separate kk GEMMs).
// ---------------------------------------------------------------------------
__global__ __launch_bounds__(256) void permute_w(
    const float* __restrict__ w, uint4* __restrict__ wp)
{
    const int u = blockIdx.x * 256 + threadIdx.x;   // 0..98303
    const int lane = u & 31;
    const int rest = u >> 5;
    const int mt = rest & 7;
    const int g  = (rest >> 3) % 6;
    const int sc = (rest >> 3) / 6;
    const int ks = g & 1;
    const int kk = g >> 1;
    const int st = sc & 15;
    const int cb = sc >> 4;

    uint4 v;
    uint32_t* o = &v.x;
#pragma unroll
    for (int rg = 0; rg < 4; ++rg) {
        const int m8 = (lane >> 2) + 8 * (rg & 1);
        const int ci = st * 32 + ks * 16 + 2 * (lane & 3) + 8 * (rg >> 1);
        const int co = cb * 128 + mt * 16 + m8;
        const float w0 = w[(size_t)co * 1536 + ci * 3 + kk];
        const float w1 = w[(size_t)co * 1536 + (ci + 1) * 3 + kk];
        o[rg] = pack_f16x2(w0, w1);
    }
    wp[u] = v;
}

// ---------------------------------------------------------------------------
// Act v4: register-window upsample, f16 output [B][C][T]. Templated input.
// ---------------------------------------------------------------------------
template <typename Tin>
__global__ __launch_bounds__(256) void act_kernel(
    const Tin* __restrict__ in, __half* __restrict__ out,
    const float* __restrict__ la, const float* __restrict__ lb,
    const float* __restrict__ fup, const float* __restrict__ fdn)
{
    __shared__ __align__(16) float sx[1040];
    __shared__ __align__(16) float sv[2064];
    __shared__ float su[12], sd[12];

    const int row = blockIdx.y;
    const int c   = row & (CCH - 1);
    const int t0  = blockIdx.x * 1024;
    const int tid = threadIdx.x;

    if (tid < 12) { su[tid] = fup[tid]; sd[tid] = fdn[tid]; }

    const Tin* xrow = in + (size_t)row * T_LEN;
#pragma unroll
    for (int it = 0; it < 5; ++it) {
        const int i = it * 256 + tid;
        if (i < 1040) {
            int g = t0 - 8 + i;
            g = min(max(g, 0), T_LEN - 1);
            sx[i] = (float)xrow[g];
        }
    }
    __syncthreads();

    const float alpha = expf(la[c]);
    const float invb  = 1.0f / (expf(lb[c]) + 1e-9f);

    float u0=su[0],u1=su[1],u2=su[2],u3=su[3],u4=su[4],u5=su[5],
          u6=su[6],u7=su[7],u8=su[8],u9=su[9],u10=su[10],u11=su[11];

    {
        float xr[12];
        const float4 a0 = *reinterpret_cast<const float4*>(&sx[tid * 4]);
        const float4 a1 = *reinterpret_cast<const float4*>(&sx[tid * 4 + 4]);
        const float4 a2 = *reinterpret_cast<const float4*>(&sx[tid * 4 + 8]);
        xr[0]=a0.x; xr[1]=a0.y; xr[2]=a0.z; xr[3]=a0.w;
        xr[4]=a1.x; xr[5]=a1.y; xr[6]=a1.z; xr[7]=a1.w;
        xr[8]=a2.x; xr[9]=a2.y; xr[10]=a2.z; xr[11]=a2.w;

        float v[8];
#pragma unroll
        for (int m = 0; m < 4; ++m) {
            float ua = u0*xr[8+m] + u2*xr[7+m] + u4*xr[6+m]
                     + u6*xr[5+m] + u8*xr[4+m] + u10*xr[3+m];
            float ub = u1*xr[8+m] + u3*xr[7+m] + u5*xr[6+m]
                     + u7*xr[5+m] + u9*xr[4+m] + u11*xr[3+m];
            ua *= 2.0f; ub *= 2.0f;
            const float sa = __sinf(ua * alpha);
            const float sb = __sinf(ub * alpha);
            v[2*m]   = ua + sa * sa * invb;
            v[2*m+1] = ub + sb * sb * invb;
        }
        float4 o0, o1;
        o0.x=v[0]; o0.y=v[1]; o0.z=v[2]; o0.w=v[3];
        o1.x=v[4]; o1.y=v[5]; o1.z=v[6]; o1.w=v[7];
        *reinterpret_cast<float4*>(&sv[tid * 8])     = o0;
        *reinterpret_cast<float4*>(&sv[tid * 8 + 4]) = o1;
    }
    if (tid < 16) {
        const int i = 2048 + tid;
        const int tp = 2 * t0 - 5 + i;
        const int sx_off = 8 - t0;
        float u;
        if (tp & 1) {
            const int h = (tp + 5) >> 1;
            const float* p = &sx[h + sx_off];
            u = u0*p[0] + u2*p[-1] + u4*p[-2] + u6*p[-3] + u8*p[-4] + u10*p[-5];
        } else {
            const int h = tp >> 1;
            const float* p = &sx[h + sx_off];
            u = u1*p[2] + u3*p[1] + u5*p[0] + u7*p[-1] + u9*p[-2] + u11*p[-3];
        }
        u *= 2.0f;
        const float s = __sinf(u * alpha);
        sv[i] = u + s * s * invb;
    }
    __syncthreads();

    if (t0 == 0 && tid < 5) sv[tid] = sv[5];
    if (t0 == T_LEN - 1024 && tid < 11) sv[2053 + tid] = sv[2052];
    __syncthreads();

    {
        float d0=sd[0],d1=sd[1],d2=sd[2],d3=sd[3],d4=sd[4],d5=sd[5],
              d6=sd[6],d7=sd[7],d8=sd[8],d9=sd[9],d10=sd[10],d11=sd[11];
        const float4 w0 = *reinterpret_cast<const float4*>(&sv[tid * 8]);
        const float4 w1 = *reinterpret_cast<const float4*>(&sv[tid * 8 + 4]);
        const float4 w2 = *reinterpret_cast<const float4*>(&sv[tid * 8 + 8]);
        const float4 w3 = *reinterpret_cast<const float4*>(&sv[tid * 8 + 12]);
        const float4 w4 = *reinterpret_cast<const float4*>(&sv[tid * 8 + 16]);
        float v[20];
        v[0]=w0.x; v[1]=w0.y; v[2]=w0.z; v[3]=w0.w;
        v[4]=w1.x; v[5]=w1.y; v[6]=w1.z; v[7]=w1.w;
        v[8]=w2.x; v[9]=w2.y; v[10]=w2.z; v[11]=w2.w;
        v[12]=w3.x; v[13]=w3.y; v[14]=w3.z; v[15]=w3.w;
        v[16]=w4.x; v[17]=w4.y; v[18]=w4.z; v[19]=w4.w;
        float z[4];
#pragma unroll
        for (int o = 0; o < 4; ++o) {
            const float* p = v + 2 * o;
            z[o] = d0*p[0] + d1*p[1] + d2*p[2] + d3*p[3] + d4*p[4] + d5*p[5]
                 + d6*p[6] + d7*p[7] + d8*p[8] + d9*p[9] + d10*p[10] + d11*p[11];
        }
        uint2 st;
        st.x = pack_f16x2(z[0], z[1]);
        st.y = pack_f16x2(z[2], z[3]);
        *reinterpret_cast<uint2*>(out + (size_t)row * T_LEN + t0 + tid * 4) = st;
    }
}

// ---------------------------------------------------------------------------
// Transpose: f16 [B][C][T] -> f16 [B][T][C].  Tile 32c x 64t.
// ---------------------------------------------------------------------------
__global__ __launch_bounds__(256) void transpose_cvt(
    const __half* __restrict__ in, __half* __restrict__ out)
{
    __shared__ float sx[32][65];
    const int t0 = blockIdx.x * 64;
    const int c0 = blockIdx.y * 32;
    const int b  = blockIdx.z;
    const int tid = threadIdx.x;

    {
        const int cl = tid >> 3;
        const int t8 = (tid & 7) * 8;
        const __half* src = in + ((size_t)(b * CCH + c0 + cl)) * T_LEN + t0 + t8;
        uint4 v = *reinterpret_cast<const uint4*>(src);
        const __half2* hp = reinterpret_cast<const __half2*>(&v);
#pragma unroll
        for (int j = 0; j < 4; ++j) {
            float2 f = __half22float2(hp[j]);
            sx[cl][t8 + 2*j]     = f.x;
            sx[cl][t8 + 2*j + 1] = f.y;
        }
    }
    __syncthreads();
    {
        const int tl = tid >> 2;
        const int cg = (tid & 3) * 8;
        uint4 o;
        o.x = pack_f16x2(sx[cg+0][tl], sx[cg+1][tl]);
        o.y = pack_f16x2(sx[cg+2][tl], sx[cg+3][tl]);
        o.z = pack_f16x2(sx[cg+4][tl], sx[cg+5][tl]);
        o.w = pack_f16x2(sx[cg+6][tl], sx[cg+7][tl]);
        *reinterpret_cast<uint4*>(out + ((size_t)(b * T_LEN + t0 + tl)) * CCH + c0 + cg) = o;
    }
}

// ---------------------------------------------------------------------------
// fp16 HMMA conv (round-12 config: 128x128, 8 warps 4x2, 2-stage pipeline).
// OUT_F16: epilogue rounds to f16 (conv1 path, resid==nullptr).
// ---------------------------------------------------------------------------
#define NST 16
#define BP  20
#define ASTAGE_W 6144                        // 24576 B
#define BSTAGE_W (130 * BP)                  // 2600 words
#define STAGE_W  (ASTAGE_W + BSTAGE_W)       // 8744 words
#define CONV_SMEM (2 * STAGE_W * 4)          // 69952 B

template <bool OUT_F16>
__global__ __launch_bounds__(256, 2)
void conv_tc(const __half* __restrict__ xt, const uint4* __restrict__ wperm,
             const float* __restrict__ bias, const float* __restrict__ resid,
             void* __restrict__ outv)
{
    extern __shared__ uint32_t Ssm[];

    const int tid  = threadIdx.x;
    const int wid  = tid >> 5;
    const int lane = tid & 31;
    const int wr   = wid >> 1;       // 0..3: M offset 32*wr
    const int wc   = wid & 1;        // 0..1: N offset 64*wc
    const int b    = blockIdx.z;
    const int cb   = blockIdx.y;
    const int co0  = cb * 128;
    const int t0   = blockIdx.x * 128;

    float acc[2][8][4];
#pragma unroll
    for (int i = 0; i < 2; i++)
#pragma unroll
        for (int j = 0; j < 8; j++)
#pragma unroll
            for (int r = 0; r < 4; r++) acc[i][j][r] = 0.0f;

    const uint32_t smem0 = smem_u32(Ssm);
    const char* browg = reinterpret_cast<const char*>(
        xt + ((size_t)(b * T_LEN + t0 - 1)) * CCH);

    const int lg = lane >> 3;
    const int lr = lane & 7;
    const uint32_t lbase = smem0 + ASTAGE_W * 4
        + (uint32_t)((wc * 64 + lr + ((lg & 2) ? 8 : 0)) * (BP * 4))
        + (uint32_t)((lg & 1) * 16);

    auto fill = [&](int st, int s) {
        const uint4* Asrc = wperm + ((size_t)(cb * 16 + st)) * 1536 + tid;
        const uint32_t dstA = smem0 + s * (STAGE_W * 4) + tid * 16;
#pragma unroll
        for (int it = 0; it < 6; ++it)
            cp_async16(dstA + it * 4096, Asrc + it * 256);
        const uint32_t dstB = smem0 + s * (STAGE_W * 4) + ASTAGE_W * 4;
        const char* bs = browg + st * 64;
#pragma unroll
        for (int it = 0; it < 3; ++it) {
            const int idx = tid + it * 256;
            if (idx < 520) {
                const int row = idx >> 2, seg = idx & 3;
                const int tg = t0 - 1 + row;
                const uint32_t sz = (tg >= 0 && tg < T_LEN) ? 16u : 0u;
                cp_async16s(dstB + row * (BP * 4) + seg * 16,
                            bs + (size_t)row * (CCH * 2) + seg * 16, sz);
            }
        }
        cp_commit();
    };

    fill(0, 0);

    for (int st = 0; st < NST; ++st) {
        const int s = st & 1;
        cp_wait<0>();
        __syncthreads();
        if (st + 1 < NST) fill(st + 1, s ^ 1);

        const uint32_t* As = Ssm + s * STAGE_W;
        const uint32_t lB = lbase + s * (STAGE_W * 4);
#pragma unroll
        for (int kk = 0; kk < 3; ++kk) {
#pragma unroll
            for (int ks = 0; ks < 2; ++ks) {
                uint4 afr[2];
#pragma unroll
                for (int mt = 0; mt < 2; ++mt)
                    afr[mt] = *reinterpret_cast<const uint4*>(
                        As + (((kk * 2 + ks) * 8 + wr * 2 + mt) * 32 + lane) * 4);
                uint2 bfr[8];
                const uint32_t bb = lB + kk * (BP * 4) + ks * 32;
#pragma unroll
                for (int ntp = 0; ntp < 4; ++ntp)
                    ldsm_x4(bfr[2*ntp].x, bfr[2*ntp].y,
                            bfr[2*ntp+1].x, bfr[2*ntp+1].y,
                            bb + ntp * (16 * BP * 4));
#pragma unroll
                for (int mt = 0; mt < 2; ++mt)
#pragma unroll
                    for (int nt = 0; nt < 8; ++nt)
                        mma_f16(acc[mt][nt],
                                reinterpret_cast<const uint32_t*>(&afr[mt]),
                                reinterpret_cast<const uint32_t*>(&bfr[nt]));
            }
        }
    }

    __syncthreads();

    // ---- epilogue ----
    const int gid = lane >> 2;
    const int tig = lane & 3;
#pragma unroll
    for (int mt = 0; mt < 2; ++mt) {
#pragma unroll
        for (int half = 0; half < 2; ++half) {
            const int co = co0 + wr * 32 + mt * 16 + gid + half * 8;
            const float bv = __ldg(bias + co);
            if (OUT_F16) {
                __half* orow = (__half*)outv + ((size_t)b * CCH + co) * T_LEN
                             + t0 + wc * 64;
#pragma unroll
                for (int nt = 0; nt < 8; ++nt) {
                    const int n = nt * 8 + tig * 2;
                    const float lo = acc[mt][nt][half * 2 + 0] + bv;
                    const float hi = acc[mt][nt][half * 2 + 1] + bv;
                    *reinterpret_cast<uint32_t*>(orow + n) = pack_f16x2(lo, hi);
                }
            } else {
                float* orow = (float*)outv + ((size_t)b * CCH + co) * T_LEN
                            + t0 + wc * 64;
                const float* rrow = resid + ((size_t)b * CCH + co) * T_LEN
                                  + t0 + wc * 64;
#pragma unroll
                for (int nt = 0; nt < 8; ++nt) {
                    const int n = nt * 8 + tig * 2;
                    float lo = acc[mt][nt][half * 2 + 0] + bv;
                    float hi = acc[mt][nt][half * 2 + 1] + bv;
                    float2 rv = *reinterpret_cast<const float2*>(rrow + n);
                    lo += rv.x; hi += rv.y;
                    float2 v; v.x = lo; v.y = hi;
                    *reinterpret_cast<float2*>(orow + n) = v;
                }
            }
        }
    }
}

// ---------------------------------------------------------------------------
extern "C" void kernel_launch(void* const* d_in, const int* in_sizes, int n_in,
                              void* d_out, int out_size)
{
    const float* x    = (const float*)d_in[0];
    const float* a1a  = (const float*)d_in[1];
    const float* a1b  = (const float*)d_in[2];
    const float* a2a  = (const float*)d_in[3];
    const float* a2b  = (const float*)d_in[4];
    const float* c1w  = (const float*)d_in[5];
    const float* c1b  = (const float*)d_in[6];
    const float* c2w  = (const float*)d_in[7];
    const float* c2b  = (const float*)d_in[8];
    const float* fup  = (const float*)d_in[9];
    const float* fdn  = (const float*)d_in[10];
    float* out = (float*)d_out;

    __half *gM, *gH, *gT;
    uint4 *wp1, *wp2;
    cudaGetSymbolAddress((void**)&gM, g_bufM);
    cudaGetSymbolAddress((void**)&gH, g_bufH);
    cudaGetSymbolAddress((void**)&gT, g_bufT);
    cudaGetSymbolAddress((void**)&wp1, g_wperm1);
    cudaGetSymbolAddress((void**)&wp2, g_wperm2);

    cudaFuncSetAttribute(conv_tc<true>,
                         cudaFuncAttributeMaxDynamicSharedMemorySize, CONV_SMEM);
    cudaFuncSetAttribute(conv_tc<false>,
                         cudaFuncAttributeMaxDynamicSharedMemorySize, CONV_SMEM);

    dim3 gAct(T_LEN / 1024, BATCH * CCH);
    dim3 gTr(T_LEN / 64, CCH / 32, BATCH);
    dim3 gConv(T_LEN / 128, CCH / 128, BATCH);

    permute_w<<<384, 256>>>(c1w, wp1);
    permute_w<<<384, 256>>>(c2w, wp2);

    act_kernel<float><<<gAct, 256>>>(x, gH, a1a, a1b, fup, fdn);
    transpose_cvt<<<gTr, 256>>>(gH, gT);
    conv_tc<true><<<gConv, 256, CONV_SMEM>>>(gT, wp1, c1b, nullptr, gM);
    act_kernel<__half><<<gAct, 256>>>(gM, gH, a2a, a2b, fup, fdn);
    transpose_cvt<<<gTr, 256>>>(gH, gT);
    conv_tc<false><<<gConv, 256, CONV_SMEM>>>(gT, wp2, c2b, x, out);
}

// round 16
// speedup vs baseline: 1.1417x; 1.0755x over previous
#include <cuda_runtime.h>
#include <cuda_fp16.h>
#include <cstdint>

#define T_LEN 8192
#define CCH   512
#define BATCH 8
#define NELEM (BATCH * CCH * T_LEN)

__device__ __half g_bufM[NELEM];            // conv1 output (f16, [B][C][T])
__device__ __half g_bufT[NELEM];            // act output, transposed (f16, [B][T][C])

// Pre-permuted f16 weights, fragment order:
// u = (((cb*16 + st)*6 + (kk*2+ks))*8 + mt)*32 + lane   (uint4 each)
#define WPERM_U4 (4 * 16 * 6 * 8 * 32)     // 98304 uint4 = 1.5 MB
__device__ uint4 g_wperm1[WPERM_U4];
__device__ uint4 g_wperm2[WPERM_U4];

// ---------------------------------------------------------------------------
__device__ __forceinline__ uint32_t smem_u32(const void* p) {
    uint32_t a;
    asm("{ .reg .u64 t; cvta.to.shared.u64 t, %1; cvt.u32.u64 %0, t; }"
        : "=r"(a) : "l"(p));
    return a;
}
__device__ __forceinline__ uint32_t pack_f16x2(float lo, float hi) {
    uint32_t r;
    asm("cvt.rn.f16x2.f32 %0, %1, %2;" : "=r"(r) : "f"(hi), "f"(lo));
    return r;
}
__device__ __forceinline__ void cp_async16(uint32_t dst, const void* src) {
    asm volatile("cp.async.cg.shared.global [%0], [%1], 16;"
                 :: "r"(dst), "l"(src));
}
__device__ __forceinline__ void cp_async16s(uint32_t dst, const void* src, uint32_t sz) {
    asm volatile("cp.async.cg.shared.global [%0], [%1], 16, %2;"
                 :: "r"(dst), "l"(src), "r"(sz));
}
__device__ __forceinline__ void cp_commit() {
    asm volatile("cp.async.commit_group;" ::: "memory");
}
template <int N>
__device__ __forceinline__ void cp_wait() {
    asm volatile("cp.async.wait_group %0;" :: "n"(N) : "memory");
}
__device__ __forceinline__ void mma_f16(float* d, const uint32_t* a, const uint32_t* b) {
    asm volatile(
        "mma.sync.aligned.m16n8k16.row.col.f32.f16.f16.f32 "
        "{%0,%1,%2,%3}, {%4,%5,%6,%7}, {%8,%9}, {%0,%1,%2,%3};"
        : "+f"(d[0]), "+f"(d[1]), "+f"(d[2]), "+f"(d[3])
        : "r"(a[0]), "r"(a[1]), "r"(a[2]), "r"(a[3]), "r"(b[0]), "r"(b[1]));
}
__device__ __forceinline__ void ldsm_x4(uint32_t& r0, uint32_t& r1,
                                        uint32_t& r2, uint32_t& r3, uint32_t addr) {
    asm volatile("ldmatrix.sync.aligned.m8n8.x4.shared.b16 {%0,%1,%2,%3}, [%4];"
                 : "=r"(r0), "=r"(r1), "=r"(r2), "=r"(r3) : "r"(addr));
}

// ---------------------------------------------------------------------------
// Weight permutation: K-dim = ci (3 separate kk GEMMs).
// ---------------------------------------------------------------------------
__global__ __launch_bounds__(256) void permute_w(
    const float* __restrict__ w, uint4* __restrict__ wp)
{
    const int u = blockIdx.x * 256 + threadIdx.x;   // 0..98303
    const int lane = u & 31;
    const int rest = u >> 5;
    const int mt = rest & 7;
    const int g  = (rest >> 3) % 6;
    const int sc = (rest >> 3) / 6;
    const int ks = g & 1;
    const int kk = g >> 1;
    const int st = sc & 15;
    const int cb = sc >> 4;

    uint4 v;
    uint32_t* o = &v.x;
#pragma unroll
    for (int rg = 0; rg < 4; ++rg) {
        const int m8 = (lane >> 2) + 8 * (rg & 1);
        const int ci = st * 32 + ks * 16 + 2 * (lane & 3) + 8 * (rg >> 1);
        const int co = cb * 128 + mt * 16 + m8;
        const float w0 = w[(size_t)co * 1536 + ci * 3 + kk];
        const float w1 = w[(size_t)co * 1536 + (ci + 1) * 3 + kk];
        o[rg] = pack_f16x2(w0, w1);
    }
    wp[u] = v;
}

// ---------------------------------------------------------------------------
// Fused Act + Transpose: in [B][C][T] (Tin) -> out f16 [B][T][C].
// Block: 64 ch x 64 t. Thread (cl=tid>>2, tg=tid&3) computes 16 consecutive t
// of channel c0+cl via sliding v-window in registers; z staged in swizzled
// f32 smem tile; coalesced [t][C] row writes.
// ---------------------------------------------------------------------------
#define SXW 81

#define CALCV(dst, ODD, HREL) do {                                            \
    float _u;                                                                 \
    if (ODD) _u = u0*xr[(HREL)]   + u2*xr[(HREL)-1] + u4*xr[(HREL)-2]         \
                + u6*xr[(HREL)-3] + u8*xr[(HREL)-4] + u10*xr[(HREL)-5];       \
    else     _u = u1*xr[(HREL)+2] + u3*xr[(HREL)+1] + u5*xr[(HREL)]           \
                + u7*xr[(HREL)-1] + u9*xr[(HREL)-2] + u11*xr[(HREL)-3];       \
    _u *= 2.0f;                                                               \
    const float _s = __sinf(_u * alpha);                                      \
    dst = _u + _s * _s * invb; } while (0)

template <typename Tin>
__global__ __launch_bounds__(256) void actT_kernel(
    const Tin* __restrict__ in, __half* __restrict__ outT,
    const float* __restrict__ la, const float* __restrict__ lb,
    const float* __restrict__ fup, const float* __restrict__ fdn)
{
    __shared__ float sx[64 * SXW];
    __shared__ float zt[64 * 64];
    __shared__ float su[12], sd[12];

    const int t0 = blockIdx.x * 64;
    const int c0 = blockIdx.y * 64;
    const int b  = blockIdx.z;
    const int tid = threadIdx.x;

    if (tid < 12) { su[tid] = fup[tid]; sd[tid] = fdn[tid]; }

    // load x window: rows c0..c0+63, cols t0-8..t0+72 (clamped)
    for (int i = tid; i < 64 * SXW; i += 256) {
        const int r = i / SXW;
        const int j = i - r * SXW;
        int g = t0 - 8 + j;
        g = min(max(g, 0), T_LEN - 1);
        sx[i] = (float)in[((size_t)(b * CCH + c0 + r)) * T_LEN + g];
    }
    __syncthreads();

    const int cl = tid >> 2;          // 0..63
    const int tg = tid & 3;           // 0..3
    const int c  = c0 + cl;
    const int tb = t0 + tg * 16;

    const float alpha = expf(la[c]);
    const float invb  = 1.0f / (expf(lb[c]) + 1e-9f);
    const float u0=su[0],u1=su[1],u2=su[2],u3=su[3],u4=su[4],u5=su[5],
                u6=su[6],u7=su[7],u8=su[8],u9=su[9],u10=su[10],u11=su[11];
    const float d0=sd[0],d1=sd[1],d2=sd[2],d3=sd[3],d4=sd[4],d5=sd[5],
                d6=sd[6],d7=sd[7],d8=sd[8],d9=sd[9],d10=sd[10],d11=sd[11];

    // register x window: X(tb-5 .. tb+20)
    float xr[26];
    {
        const float* row = &sx[cl * SXW + tg * 16 + 3];
#pragma unroll
        for (int j = 0; j < 26; ++j) xr[j] = row[j];
    }

    // prime v window: vw[j] = v(2*tb-5+j), j=0..9
    float vw[12];
#pragma unroll
    for (int j = 0; j < 10; ++j) {
        if (j & 1) { CALCV(vw[j], false, ((j - 5) / 2 + 5)); }
        else       { CALCV(vw[j], true,  (j / 2 + 5)); }
    }
    if (tb == 0) {
        const float v0 = vw[5];
        vw[0] = v0; vw[1] = v0; vw[2] = v0; vw[3] = v0; vw[4] = v0;
    }

    float vhi = 0.0f;
#pragma unroll
    for (int o = 0; o < 16; ++o) {
        const int t = tb + o;
        float va, vb;
        CALCV(va, true,  (o + 10));   // tp = 2t+5 (odd)
        CALCV(vb, false, (o + 8));    // tp = 2t+6 (even)
        // high-edge replication: v(tp>2T-1) := v(2T-1)
        if (2 * t + 5 == 2 * T_LEN - 1) vhi = va;
        if (2 * t + 5 >  2 * T_LEN - 1) va = vhi;
        if (2 * t + 6 >  2 * T_LEN - 1) vb = vhi;
        vw[10] = va; vw[11] = vb;

        const float z = d0*vw[0] + d1*vw[1] + d2*vw[2] + d3*vw[3]
                      + d4*vw[4] + d5*vw[5] + d6*vw[6] + d7*vw[7]
                      + d8*vw[8] + d9*vw[9] + d10*vw[10] + d11*vw[11];

        const int tt  = tg * 16 + o;
        const int swz = (tt + (tt >> 2)) & 31;
        zt[tt * 64 + (cl ^ swz)] = z;

#pragma unroll
        for (int j = 0; j < 10; ++j) vw[j] = vw[j + 2];
    }
    __syncthreads();

    // write out: 64 rows x 128B ([b][t0+tt][C] at c0), coalesced uint4 segs
#pragma unroll
    for (int iter = 0; iter < 2; ++iter) {
        const int idx = tid + iter * 256;
        const int tt  = idx >> 3;
        const int seg = idx & 7;
        const int swz = (tt + (tt >> 2)) & 31;
        uint4 o4;
        uint32_t* ow = &o4.x;
#pragma unroll
        for (int k = 0; k < 4; ++k) {
            const int ca = seg * 8 + 2 * k;
            const float za = zt[tt * 64 + (ca ^ swz)];
            const float zb = zt[tt * 64 + ((ca + 1) ^ swz)];
            ow[k] = pack_f16x2(za, zb);
        }
        *reinterpret_cast<uint4*>(
            outT + ((size_t)(b * T_LEN + t0 + tt)) * CCH + c0 + seg * 8) = o4;
    }
}

// ---------------------------------------------------------------------------
// fp16 HMMA conv (round-12 config: 128x128, 8 warps 4x2, 2-stage pipeline).
// OUT_F16: epilogue rounds to f16 (conv1 path, resid==nullptr).
// ---------------------------------------------------------------------------
#define NST 16
#define BP  20
#define ASTAGE_W 6144                        // 24576 B
#define BSTAGE_W (130 * BP)                  // 2600 words
#define STAGE_W  (ASTAGE_W + BSTAGE_W)       // 8744 words
#define CONV_SMEM (2 * STAGE_W * 4)          // 69952 B

template <bool OUT_F16>
__global__ __launch_bounds__(256, 2)
void conv_tc(const __half* __restrict__ xt, const uint4* __restrict__ wperm,
             const float* __restrict__ bias, const float* __restrict__ resid,
             void* __restrict__ outv)
{
    extern __shared__ uint32_t Ssm[];

    const int tid  = threadIdx.x;
    const int wid  = tid >> 5;
    const int lane = tid & 31;
    const int wr   = wid >> 1;       // 0..3: M offset 32*wr
    const int wc   = wid & 1;        // 0..1: N offset 64*wc
    const int b    = blockIdx.z;
    const int cb   = blockIdx.y;
    const int co0  = cb * 128;
    const int t0   = blockIdx.x * 128;

    float acc[2][8][4];
#pragma unroll
    for (int i = 0; i < 2; i++)
#pragma unroll
        for (int j = 0; j < 8; j++)
#pragma unroll
            for (int r = 0; r < 4; r++) acc[i][j][r] = 0.0f;

    const uint32_t smem0 = smem_u32(Ssm);
    const char* browg = reinterpret_cast<const char*>(
        xt + ((size_t)(b * T_LEN + t0 - 1)) * CCH);

    const int lg = lane >> 3;
    const int lr = lane & 7;
    const uint32_t lbase = smem0 + ASTAGE_W * 4
        + (uint32_t)((wc * 64 + lr + ((lg & 2) ? 8 : 0)) * (BP * 4))
        + (uint32_t)((lg & 1) * 16);

    auto fill = [&](int st, int s) {
        const uint4* Asrc = wperm + ((size_t)(cb * 16 + st)) * 1536 + tid;
        const uint32_t dstA = smem0 + s * (STAGE_W * 4) + tid * 16;
#pragma unroll
        for (int it = 0; it < 6; ++it)
            cp_async16(dstA + it * 4096, Asrc + it * 256);
        const uint32_t dstB = smem0 + s * (STAGE_W * 4) + ASTAGE_W * 4;
        const char* bs = browg + st * 64;
#pragma unroll
        for (int it = 0; it < 3; ++it) {
            const int idx = tid + it * 256;
            if (idx < 520) {
                const int row = idx >> 2, seg = idx & 3;
                const int tg = t0 - 1 + row;
                const uint32_t sz = (tg >= 0 && tg < T_LEN) ? 16u : 0u;
                cp_async16s(dstB + row * (BP * 4) + seg * 16,
                            bs + (size_t)row * (CCH * 2) + seg * 16, sz);
            }
        }
        cp_commit();
    };

    fill(0, 0);

    for (int st = 0; st < NST; ++st) {
        const int s = st & 1;
        cp_wait<0>();
        __syncthreads();
        if (st + 1 < NST) fill(st + 1, s ^ 1);

        const uint32_t* As = Ssm + s * STAGE_W;
        const uint32_t lB = lbase + s * (STAGE_W * 4);
#pragma unroll
        for (int kk = 0; kk < 3; ++kk) {
#pragma unroll
            for (int ks = 0; ks < 2; ++ks) {
                uint4 afr[2];
#pragma unroll
                for (int mt = 0; mt < 2; ++mt)
                    afr[mt] = *reinterpret_cast<const uint4*>(
                        As + (((kk * 2 + ks) * 8 + wr * 2 + mt) * 32 + lane) * 4);
                uint2 bfr[8];
                const uint32_t bb = lB + kk * (BP * 4) + ks * 32;
#pragma unroll
                for (int ntp = 0; ntp < 4; ++ntp)
                    ldsm_x4(bfr[2*ntp].x, bfr[2*ntp].y,
                            bfr[2*ntp+1].x, bfr[2*ntp+1].y,
                            bb + ntp * (16 * BP * 4));
#pragma unroll
                for (int mt = 0; mt < 2; ++mt)
#pragma unroll
                    for (int nt = 0; nt < 8; ++nt)
                        mma_f16(acc[mt][nt],
                                reinterpret_cast<const uint32_t*>(&afr[mt]),
                                reinterpret_cast<const uint32_t*>(&bfr[nt]));
            }
        }
    }

    __syncthreads();

    // ---- epilogue ----
    const int gid = lane >> 2;
    const int tig = lane & 3;
#pragma unroll
    for (int mt = 0; mt < 2; ++mt) {
#pragma unroll
        for (int half = 0; half < 2; ++half) {
            const int co = co0 + wr * 32 + mt * 16 + gid + half * 8;
            const float bv = __ldg(bias + co);
            if (OUT_F16) {
                __half* orow = (__half*)outv + ((size_t)b * CCH + co) * T_LEN
                             + t0 + wc * 64;
#pragma unroll
                for (int nt = 0; nt < 8; ++nt) {
                    const int n = nt * 8 + tig * 2;
                    const float lo = acc[mt][nt][half * 2 + 0] + bv;
                    const float hi = acc[mt][nt][half * 2 + 1] + bv;
                    *reinterpret_cast<uint32_t*>(orow + n) = pack_f16x2(lo, hi);
                }
            } else {
                float* orow = (float*)outv + ((size_t)b * CCH + co) * T_LEN
                            + t0 + wc * 64;
                const float* rrow = resid + ((size_t)b * CCH + co) * T_LEN
                                  + t0 + wc * 64;
#pragma unroll
                for (int nt = 0; nt < 8; ++nt) {
                    const int n = nt * 8 + tig * 2;
                    float lo = acc[mt][nt][half * 2 + 0] + bv;
                    float hi = acc[mt][nt][half * 2 + 1] + bv;
                    float2 rv = *reinterpret_cast<const float2*>(rrow + n);
                    lo += rv.x; hi += rv.y;
                    float2 v; v.x = lo; v.y = hi;
                    *reinterpret_cast<float2*>(orow + n) = v;
                }
            }
        }
    }
}

// ---------------------------------------------------------------------------
extern "C" void kernel_launch(void* const* d_in, const int* in_sizes, int n_in,
                              void* d_out, int out_size)
{
    const float* x    = (const float*)d_in[0];
    const float* a1a  = (const float*)d_in[1];
    const float* a1b  = (const float*)d_in[2];
    const float* a2a  = (const float*)d_in[3];
    const float* a2b  = (const float*)d_in[4];
    const float* c1w  = (const float*)d_in[5];
    const float* c1b  = (const float*)d_in[6];
    const float* c2w  = (const float*)d_in[7];
    const float* c2b  = (const float*)d_in[8];
    const float* fup  = (const float*)d_in[9];
    const float* fdn  = (const float*)d_in[10];
    float* out = (float*)d_out;

    __half *gM, *gT;
    uint4 *wp1, *wp2;
    cudaGetSymbolAddress((void**)&gM, g_bufM);
    cudaGetSymbolAddress((void**)&gT, g_bufT);
    cudaGetSymbolAddress((void**)&wp1, g_wperm1);
    cudaGetSymbolAddress((void**)&wp2, g_wperm2);

    cudaFuncSetAttribute(conv_tc<true>,
                         cudaFuncAttributeMaxDynamicSharedMemorySize, CONV_SMEM);
    cudaFuncSetAttribute(conv_tc<false>,
                         cudaFuncAttributeMaxDynamicSharedMemorySize, CONV_SMEM);

    dim3 gActT(T_LEN / 64, CCH / 64, BATCH);
    dim3 gConv(T_LEN / 128, CCH / 128, BATCH);

    permute_w<<<384, 256>>>(c1w, wp1);
    permute_w<<<384, 256>>>(c2w, wp2);

    actT_kernel<float><<<gActT, 256>>>(x, gT, a1a, a1b, fup, fdn);
    conv_tc<true><<<gConv, 256, CONV_SMEM>>>(gT, wp1, c1b, nullptr, gM);
    actT_kernel<__half><<<gActT, 256>>>(gM, gT, a2a, a2b, fup, fdn);
    conv_tc<false><<<gConv, 256, CONV_SMEM>>>(gT, wp2, c2b, x, out);
}